// round 12
// baseline (speedup 1.0000x reference)
#include <cuda_runtime.h>
#include <math.h>

#define BB 4
#define TT 2048
#define DD 1024
#define HH 16
#define HDIM 64
#define MM (BB*TT)   /* 8192 */
#define LOW_W 64
#define LOW_A 64
#define LOW_G 160
#define DECAY_SCALE (-0.6065306597126334f)
#define GN_EPS (64.0f*1e-5f)

// ---------------- scratch (device globals: allocation is banned) ----------
__device__ float g_xr[MM*DD];
__device__ float g_xw[MM*DD];
__device__ float g_xk[MM*DD];
__device__ float g_xv[MM*DD];
__device__ float g_xa[MM*DD];
__device__ float g_xg[MM*DD];
__device__ float g_r [MM*DD];
__device__ float g_w [MM*DD];   // holds exp(w) after the w GEMM (ACT=4)
__device__ float g_k [MM*DD];
__device__ float g_v [MM*DD];
__device__ float g_a [MM*DD];
__device__ float g_g [MM*DD];
__device__ float g_kk[MM*DD];   // holds -kk (normalized) after prep
__device__ float g_b [MM*DD];   // holds kk*a after prep
__device__ float g_o [MM*DD];
__device__ float g_y [MM*DD];
__device__ float g_uw[MM*LOW_W];
__device__ float g_ua[MM*LOW_A];
__device__ float g_ug[MM*LOW_G];

// ---------------- helpers -------------------------------------------------
__device__ __forceinline__ float f2tf32(float x) {
    unsigned u;
    asm("cvt.rna.tf32.f32 %0, %1;" : "=r"(u) : "f"(x));
    return __uint_as_float(u);
}

__device__ __forceinline__ void mma_tf32(float* c, const unsigned* a, const unsigned* b) {
    asm volatile(
        "mma.sync.aligned.m16n8k8.row.col.f32.tf32.tf32.f32 "
        "{%0,%1,%2,%3}, {%4,%5,%6,%7}, {%8,%9}, {%0,%1,%2,%3};\n"
        : "+f"(c[0]), "+f"(c[1]), "+f"(c[2]), "+f"(c[3])
        : "r"(a[0]), "r"(a[1]), "r"(a[2]), "r"(a[3]), "r"(b[0]), "r"(b[1]));
}

__device__ __forceinline__ float apply_act(float v, int ACT) {
    if (ACT == 1) return tanhf(v);
    if (ACT == 2) return 1.f / (1.f + expf(-v));
    if (ACT == 3) return DECAY_SCALE * (1.f / (1.f + expf(-v)));
    if (ACT == 4) return expf(DECAY_SCALE * (1.f / (1.f + expf(-v))));
    return v;
}

// ---------------- mix pre-pass: build the 6 token-shifted inputs ----------
__global__ void mix_kernel(const float* __restrict__ x,
                           const float* __restrict__ m_r, const float* __restrict__ m_w,
                           const float* __restrict__ m_k, const float* __restrict__ m_v,
                           const float* __restrict__ m_a, const float* __restrict__ m_g)
{
    int i = blockIdx.x * blockDim.x + threadIdx.x;   // float4 index
    if (i >= MM * DD / 4) return;
    int c4 = i & (DD / 4 - 1);
    int m  = i >> 8;                                  // token row (D/4 = 256)
    int t  = m & (TT - 1);
    const float4* x4 = (const float4*)x;
    float4 xv = x4[i];
    float4 pv = t ? x4[i - DD / 4] : make_float4(0.f, 0.f, 0.f, 0.f);
    float4 d  = make_float4(pv.x - xv.x, pv.y - xv.y, pv.z - xv.z, pv.w - xv.w);

#define APPLY(MIX, OUT) { \
    float4 mm = ((const float4*)MIX)[c4]; \
    float4 o; \
    o.x = xv.x + d.x * mm.x; o.y = xv.y + d.y * mm.y; \
    o.z = xv.z + d.z * mm.z; o.w = xv.w + d.w * mm.w; \
    ((float4*)OUT)[i] = o; }
    APPLY(m_r, g_xr); APPLY(m_w, g_xw); APPLY(m_k, g_xk);
    APPLY(m_v, g_xv); APPLY(m_a, g_xa); APPLY(m_g, g_xg);
#undef APPLY
}

// ---------------- tf32 tensor-core GEMM, packed-fragment smem -------------
// A smem: [ks][rb][g][tg][quad], rb stride ARB=140 (== 12 mod 32) + a
// bit-shuffled loader row map -> A STS is 2-way banked.
// Fragment reads: A = one LDS.128, B = one LDS.64, conflict-free.
template<int BN_, int WARPS_M, int WARPS_N, int ACT>
__global__ __launch_bounds__(256)
void gemm_tf32(const float* __restrict__ A, const float* __restrict__ B,
               float* __restrict__ C, int N, int K,
               const float* __restrict__ bias)
{
    constexpr int BM = 128, BK = 16;
    constexpr int WMT = BM / WARPS_M;
    constexpr int WNT = BN_ / WARPS_N;
    constexpr int MF = WMT / 16, NF = WNT / 8;
    constexpr int ARB = 140;
    constexpr int AKS = 8 * ARB;
    constexpr int ASZ = 2 * AKS;
    constexpr int BKS = BN_ * 8;
    constexpr int BSZ = 2 * BKS;
    constexpr int BQ    = BN_ / 4;
    constexpr int RLOAD = 256 / BQ;
    constexpr int PASS  = 16 / RLOAD;

    __shared__ alignas(16) float As[2][ASZ];
    __shared__ alignas(16) float Bs[2][BSZ];

    int tid  = threadIdx.x;
    int lane = tid & 31, warp = tid >> 5;
    int g  = lane >> 2, tg = lane & 3;
    int wm = (warp % WARPS_M) * WMT;
    int wn = (warp / WARPS_M) * WNT;
    int rb0 = wm >> 4;

    int rowBase = blockIdx.y * BM;
    int colBase = blockIdx.x * BN_;

    int t6 = tid & 63;
    int ll = t6 & 31, wbit = t6 >> 5;
    int arow = ((ll >> 2) & 3) * 16 + ((ll >> 1) & 1) * 8
             + ((ll & 1) + 2 * ((ll >> 4) & 1) + 4 * wbit);
    int ac4 = tid >> 6;
    int a_ks = ac4 >> 1, a_half = ac4 & 1;
    int bkr  = tid % RLOAD, bc4 = tid / RLOAD;

    float acc[MF][NF][4];
#pragma unroll
    for (int i = 0; i < MF; i++)
#pragma unroll
        for (int j = 0; j < NF; j++)
#pragma unroll
            for (int q = 0; q < 4; q++) acc[i][j][q] = 0.f;

    float4 ra[2], rbv[PASS];
    const int kTiles = K / BK;

#define LOAD_TILE(KT) { \
    _Pragma("unroll") \
    for (int p = 0; p < 2; p++) { \
        int r = rowBase + arow + p * 64; \
        ra[p] = *(const float4*)(A + (size_t)r * K + (KT) * BK + ac4 * 4); \
    } \
    _Pragma("unroll") \
    for (int p = 0; p < PASS; p++) { \
        int kr = bkr + p * RLOAD; \
        int cc = colBase + bc4 * 4; \
        rbv[p] = (cc < N) ? *(const float4*)(B + (size_t)((KT) * BK + kr) * N + cc) \
                          : make_float4(0.f, 0.f, 0.f, 0.f); \
    } }

#define STORE_TILE(BUF) { \
    _Pragma("unroll") \
    for (int p = 0; p < 2; p++) { \
        int r = arow + 64 * p; \
        int rb = r >> 4, gg = r & 7, hi = (r >> 3) & 1; \
        float* d = &As[BUF][a_ks * AKS + rb * ARB + gg * 16 + hi + 2 * a_half]; \
        d[0]  = f2tf32(ra[p].x); d[4]  = f2tf32(ra[p].y); \
        d[8]  = f2tf32(ra[p].z); d[12] = f2tf32(ra[p].w); \
    } \
    _Pragma("unroll") \
    for (int p = 0; p < PASS; p++) { \
        int kr = bkr + p * RLOAD; \
        int ks = kr >> 3, kl = kr & 7, btg = kl & 3, hs = kl >> 2; \
        float* d = &Bs[BUF][ks * BKS + (bc4 * 4) * 8 + btg * 2 + hs]; \
        d[0]  = f2tf32(rbv[p].x); d[8]  = f2tf32(rbv[p].y); \
        d[16] = f2tf32(rbv[p].z); d[24] = f2tf32(rbv[p].w); \
    } }

    LOAD_TILE(0);
    STORE_TILE(0);
    __syncthreads();

    int cur = 0;
    for (int kt = 1; kt <= kTiles; kt++) {
        if (kt < kTiles) LOAD_TILE(kt);

#pragma unroll
        for (int ks = 0; ks < 2; ks++) {
            unsigned af[MF][4], bf[NF][2];
#pragma unroll
            for (int i = 0; i < MF; i++) {
                float4 v = *(const float4*)&As[cur][ks * AKS + (rb0 + i) * ARB + g * 16 + tg * 4];
                af[i][0] = __float_as_uint(v.x); af[i][1] = __float_as_uint(v.y);
                af[i][2] = __float_as_uint(v.z); af[i][3] = __float_as_uint(v.w);
            }
#pragma unroll
            for (int j = 0; j < NF; j++) {
                float2 v = *(const float2*)&Bs[cur][ks * BKS + (wn + j * 8 + g) * 8 + tg * 2];
                bf[j][0] = __float_as_uint(v.x); bf[j][1] = __float_as_uint(v.y);
            }
#pragma unroll
            for (int i = 0; i < MF; i++)
#pragma unroll
                for (int j = 0; j < NF; j++)
                    mma_tf32(acc[i][j], af[i], bf[j]);
        }

        if (kt < kTiles) {
            int nxt = cur ^ 1;
            STORE_TILE(nxt);
        }
        __syncthreads();
        cur ^= 1;
    }
#undef LOAD_TILE
#undef STORE_TILE

#pragma unroll
    for (int i = 0; i < MF; i++) {
#pragma unroll
        for (int j = 0; j < NF; j++) {
            int r0 = rowBase + wm + i * 16 + g;
            int c0 = colBase + wn + j * 8 + 2 * tg;
#pragma unroll
            for (int q = 0; q < 4; q++) {
                int rr = r0 + (q >> 1) * 8;
                int cc = c0 + (q & 1);
                if (cc < N) {
                    float v = acc[i][j][q];
                    if (bias) v += bias[cc];
                    v = apply_act(v, ACT);
                    C[(size_t)rr * N + cc] = v;
                }
            }
        }
    }
}

// ---------------- prep: kk = l2norm(k*k_k); b = kk*a; nk = -kk; k rescale --
__global__ void prep_kernel(const float* __restrict__ k_k,
                            const float* __restrict__ k_a)
{
    int hidx = blockIdx.x;             // MM*HH
    int m = hidx >> 4, h = hidx & 15;
    int lane = threadIdx.x;            // 32
    size_t base = (size_t)m * DD + h * HDIM;
    int d0 = h * HDIM + lane, d1 = d0 + 32;

    float k0 = g_k[base + lane], k1 = g_k[base + lane + 32];
    float q0 = k0 * k_k[d0],     q1 = k1 * k_k[d1];
    float ss = q0 * q0 + q1 * q1;
#pragma unroll
    for (int o = 16; o > 0; o >>= 1) ss += __shfl_xor_sync(0xffffffffu, ss, o);
    float inv = 1.f / fmaxf(sqrtf(ss), 1e-12f);
    float kk0 = q0 * inv, kk1 = q1 * inv;

    float a0 = g_a[base + lane], a1 = g_a[base + lane + 32];
    g_kk[base + lane]      = -kk0;
    g_kk[base + lane + 32] = -kk1;
    g_b[base + lane]       = kk0 * a0;
    g_b[base + lane + 32]  = kk1 * a1;
    g_k[base + lane]       = k0 * (1.f + (a0 - 1.f) * k_a[d0]);
    g_k[base + lane + 32]  = k1 * (1.f + (a1 - 1.f) * k_a[d1]);
}

// ---------------- sequential delta-rule scan v4 (register-direct) ----------
// Each thread LDGs its OWN compute slice (8 floats of w/r/k/b/nk + v scalar)
// directly into registers -> no smem staging, no syncwarp, no LDS on the
// critical path. Two fully-unrolled register slot sets (double buffer);
// same-address lanes dedupe in L1tex so L2 traffic is unchanged.
// Warp = 4 rows x 8 col-threads, 8 state cols/thread (round-8 layout).
#define GROUPS 16
#define ROWS   4
__global__ void scan_kernel()
{
    int idx = blockIdx.x;
    int g  = idx & (GROUPS - 1);
    int bh = idx >> 4;
    int b = bh >> 4, h = bh & 15;
    int tid = threadIdx.x;
    int row = tid >> 3;       // 0..3
    int c   = tid & 7;        // 0..7
    int c0  = c * 8;

    size_t basebh = ((size_t)b * TT) * DD + h * HDIM;
    int vofs = g * ROWS + row;

    float S[8];
#pragma unroll
    for (int j = 0; j < 8; j++) S[j] = 0.f;

    // two register slot sets, all accesses via unrolled constant indices
    float W0[8], R0[8], Kk0[8], Bb0[8], Nn0[8], V0;
    float W1[8], R1[8], Kk1[8], Bb1[8], Nn1[8], V1;

#define LOADS(s, T) { \
    size_t pb = basebh + (size_t)(T) * DD + c0; \
    *(float4*)&W##s[0]  = *(const float4*)(g_w  + pb); \
    *(float4*)&W##s[4]  = *(const float4*)(g_w  + pb + 4); \
    *(float4*)&R##s[0]  = *(const float4*)(g_r  + pb); \
    *(float4*)&R##s[4]  = *(const float4*)(g_r  + pb + 4); \
    *(float4*)&Kk##s[0] = *(const float4*)(g_k  + pb); \
    *(float4*)&Kk##s[4] = *(const float4*)(g_k  + pb + 4); \
    *(float4*)&Bb##s[0] = *(const float4*)(g_b  + pb); \
    *(float4*)&Bb##s[4] = *(const float4*)(g_b  + pb + 4); \
    *(float4*)&Nn##s[0] = *(const float4*)(g_kk + pb); \
    *(float4*)&Nn##s[4] = *(const float4*)(g_kk + pb + 4); \
    V##s = g_v[basebh + (size_t)(T) * DD + vofs]; }

#define STEP(s, T) { \
    float pa0 = 0.f, pa1 = 0.f; \
    _Pragma("unroll") \
    for (int j = 0; j < 4; j++) pa0 = fmaf(S[j],     Nn##s[j],     pa0); \
    _Pragma("unroll") \
    for (int j = 0; j < 4; j++) pa1 = fmaf(S[j + 4], Nn##s[j + 4], pa1); \
    float pa = pa0 + pa1; \
    pa += __shfl_xor_sync(0xffffffffu, pa, 1); \
    pa += __shfl_xor_sync(0xffffffffu, pa, 2); \
    pa += __shfl_xor_sync(0xffffffffu, pa, 4); \
    float po0 = 0.f, po1 = 0.f; \
    _Pragma("unroll") \
    for (int j = 0; j < 8; j++) { \
        float s2 = fmaf(S[j], W##s[j], fmaf(pa, Bb##s[j], V##s * Kk##s[j])); \
        S[j] = s2; \
        if (j < 4) po0 = fmaf(s2, R##s[j], po0); \
        else       po1 = fmaf(s2, R##s[j], po1); \
    } \
    float po = po0 + po1; \
    po += __shfl_xor_sync(0xffffffffu, po, 1); \
    po += __shfl_xor_sync(0xffffffffu, po, 2); \
    po += __shfl_xor_sync(0xffffffffu, po, 4); \
    if (c == 0) g_o[basebh + (size_t)(T) * DD + vofs] = po; \
    if ((T) + 2 < TT) LOADS(s, (T) + 2); }

    LOADS(0, 0);
    LOADS(1, 1);
    for (int t = 0; t < TT; t += 2) {
        STEP(0, t);
        STEP(1, t + 1);
    }
#undef LOADS
#undef STEP
}

// ---------------- post: GroupNorm(head) + corr + gate ---------------------
__global__ void post_kernel(const float* __restrict__ r_k,
                            const float* __restrict__ gnw,
                            const float* __restrict__ gnb)
{
    int hidx = blockIdx.x;
    int m = hidx >> 4, h = hidx & 15;
    int lane = threadIdx.x;
    size_t base = (size_t)m * DD + h * HDIM;
    int d0 = h * HDIM + lane, d1 = d0 + 32;

    float o0 = g_o[base + lane], o1 = g_o[base + lane + 32];
    float s = o0 + o1;
#pragma unroll
    for (int o = 16; o > 0; o >>= 1) s += __shfl_xor_sync(0xffffffffu, s, o);
    float mu = s * (1.f / 64.f);
    float e0 = o0 - mu, e1 = o1 - mu;
    float vs = e0 * e0 + e1 * e1;
#pragma unroll
    for (int o = 16; o > 0; o >>= 1) vs += __shfl_xor_sync(0xffffffffu, vs, o);
    float inv = rsqrtf(vs * (1.f / 64.f) + GN_EPS);

    float on0 = e0 * inv * gnw[d0] + gnb[d0];
    float on1 = e1 * inv * gnw[d1] + gnb[d1];

    float dot = g_r[base + lane]      * g_k[base + lane]      * r_k[d0]
              + g_r[base + lane + 32] * g_k[base + lane + 32] * r_k[d1];
#pragma unroll
    for (int o = 16; o > 0; o >>= 1) dot += __shfl_xor_sync(0xffffffffu, dot, o);

    g_y[base + lane]      = (on0 + dot * g_v[base + lane])      * g_g[base + lane];
    g_y[base + lane + 32] = (on1 + dot * g_v[base + lane + 32]) * g_g[base + lane + 32];
}

// ---------------------------------------------------------------------------
extern "C" void kernel_launch(void* const* d_in, const int* in_sizes, int n_in,
                              void* d_out, int out_size)
{
    const float* x     = (const float*)d_in[0];
    const float* mix_r = (const float*)d_in[1];
    const float* mix_w = (const float*)d_in[2];
    const float* mix_k = (const float*)d_in[3];
    const float* mix_v = (const float*)d_in[4];
    const float* mix_a = (const float*)d_in[5];
    const float* mix_g = (const float*)d_in[6];
    const float* k_k   = (const float*)d_in[7];
    const float* k_a   = (const float*)d_in[8];
    const float* r_k   = (const float*)d_in[9];
    const float* Wr    = (const float*)d_in[10];
    const float* Wk    = (const float*)d_in[11];
    const float* Wv    = (const float*)d_in[12];
    const float* Wo    = (const float*)d_in[13];
    const float* wA    = (const float*)d_in[14];
    const float* wB    = (const float*)d_in[15];
    const float* w_bias= (const float*)d_in[16];
    const float* aA    = (const float*)d_in[17];
    const float* aB    = (const float*)d_in[18];
    const float* a_bias= (const float*)d_in[19];
    const float* gA    = (const float*)d_in[20];
    const float* gB    = (const float*)d_in[21];
    const float* gnw   = (const float*)d_in[22];
    const float* gnb   = (const float*)d_in[23];
    float* out = (float*)d_out;

    float *pxr, *pxw, *pxk, *pxv, *pxa, *pxg;
    float *pr, *pw, *pk, *pv, *pa, *pg, *py, *puw, *pua, *pug;
    cudaGetSymbolAddress((void**)&pxr, g_xr);
    cudaGetSymbolAddress((void**)&pxw, g_xw);
    cudaGetSymbolAddress((void**)&pxk, g_xk);
    cudaGetSymbolAddress((void**)&pxv, g_xv);
    cudaGetSymbolAddress((void**)&pxa, g_xa);
    cudaGetSymbolAddress((void**)&pxg, g_xg);
    cudaGetSymbolAddress((void**)&pr,  g_r);
    cudaGetSymbolAddress((void**)&pw,  g_w);
    cudaGetSymbolAddress((void**)&pk,  g_k);
    cudaGetSymbolAddress((void**)&pv,  g_v);
    cudaGetSymbolAddress((void**)&pa,  g_a);
    cudaGetSymbolAddress((void**)&pg,  g_g);
    cudaGetSymbolAddress((void**)&py,  g_y);
    cudaGetSymbolAddress((void**)&puw, g_uw);
    cudaGetSymbolAddress((void**)&pua, g_ua);
    cudaGetSymbolAddress((void**)&pug, g_ug);

    // 1. token-shift mix -> 6 mixed inputs
    mix_kernel<<<MM * DD / 4 / 256, 256>>>(x, mix_r, mix_w, mix_k, mix_v, mix_a, mix_g);

    dim3 blk(256);
    dim3 grdBig(DD / 128, MM / 128);            // (8, 64) : N=1024
    dim3 grdUp64(1, MM / 128);                  // (1, 64) : N=64
    dim3 grdUp160((LOW_G + 63) / 64, MM / 128); // (3, 64) : N=160

    // 2. big projections (tf32 tensor cores)
    gemm_tf32<128,2,4,0><<<grdBig, blk>>>(pxr, Wr, pr, DD, DD, nullptr);
    gemm_tf32<128,2,4,0><<<grdBig, blk>>>(pxk, Wk, pk, DD, DD, nullptr);
    gemm_tf32<128,2,4,0><<<grdBig, blk>>>(pxv, Wv, pv, DD, DD, nullptr);

    // 3. w lora: tanh(xw@wA) @ wB + bias -> exp(DECAY_SCALE*sigmoid(.)) fused
    gemm_tf32<64,4,2,1><<<grdUp64, blk>>>(pxw, wA, puw, LOW_W, DD, nullptr);
    gemm_tf32<128,2,4,4><<<grdBig, blk>>>(puw, wB, pw, DD, LOW_W, w_bias);

    // 4. a lora: (xa@aA) @ aB + bias -> sigmoid
    gemm_tf32<64,4,2,0><<<grdUp64, blk>>>(pxa, aA, pua, LOW_A, DD, nullptr);
    gemm_tf32<128,2,4,2><<<grdBig, blk>>>(pua, aB, pa, DD, LOW_A, a_bias);

    // 5. g lora: sigmoid(xg@gA) @ gB
    gemm_tf32<64,4,2,2><<<grdUp160, blk>>>(pxg, gA, pug, LOW_G, DD, nullptr);
    gemm_tf32<128,2,4,0><<<grdBig, blk>>>(pug, gB, pg, DD, LOW_G, nullptr);

    // 6. kk normalize + b/nk precompute + k rescale
    prep_kernel<<<MM * HH, 32>>>(k_k, k_a);

    // 7. sequential generalized delta-rule scan (v4 register-direct)
    scan_kernel<<<BB * HH * GROUPS, 32>>>();

    // 8. GroupNorm + correction + gate
    post_kernel<<<MM * HH, 32>>>(r_k, gnw, gnb);

    // 9. output projection
    gemm_tf32<128,2,4,0><<<grdBig, blk>>>(py, Wo, out, DD, DD, nullptr);
}

// round 13
// speedup vs baseline: 1.0925x; 1.0925x over previous
#include <cuda_runtime.h>
#include <math.h>

#define BB 4
#define TT 2048
#define DD 1024
#define HH 16
#define HDIM 64
#define MM (BB*TT)   /* 8192 */
#define LOW_W 64
#define LOW_A 64
#define LOW_G 160
#define DECAY_SCALE (-0.6065306597126334f)
#define GN_EPS (64.0f*1e-5f)
#define TPAIR (TT/2)

// ---------------- scratch (device globals: allocation is banned) ----------
__device__ float g_xr[MM*DD];
__device__ float g_xw[MM*DD];
__device__ float g_xk[MM*DD];
__device__ float g_xv[MM*DD];
__device__ float g_xa[MM*DD];
__device__ float g_xg[MM*DD];
__device__ float g_r [MM*DD];
__device__ float g_w [MM*DD];   // holds exp(w) after the w GEMM (ACT=4)
__device__ float g_k [MM*DD];
__device__ float g_v [MM*DD];
__device__ float g_a [MM*DD];
__device__ float g_g [MM*DD];
__device__ float g_kk[MM*DD];   // holds -kk (normalized) after prep
__device__ float g_b [MM*DD];   // holds kk*a after prep
__device__ float g_o [MM*DD];
__device__ float g_y [MM*DD];
__device__ float g_uw[MM*LOW_W];
__device__ float g_ua[MM*LOW_A];
__device__ float g_ug[MM*LOW_G];
__device__ float g_c1[BB*HH*TPAIR];   // b_t · nk_{t+1} per even t
__device__ float g_c2[BB*HH*TPAIR];   // k_t · nk_{t+1} per even t

// ---------------- helpers -------------------------------------------------
__device__ __forceinline__ float f2tf32(float x) {
    unsigned u;
    asm("cvt.rna.tf32.f32 %0, %1;" : "=r"(u) : "f"(x));
    return __uint_as_float(u);
}

__device__ __forceinline__ void mma_tf32(float* c, const unsigned* a, const unsigned* b) {
    asm volatile(
        "mma.sync.aligned.m16n8k8.row.col.f32.tf32.tf32.f32 "
        "{%0,%1,%2,%3}, {%4,%5,%6,%7}, {%8,%9}, {%0,%1,%2,%3};\n"
        : "+f"(c[0]), "+f"(c[1]), "+f"(c[2]), "+f"(c[3])
        : "r"(a[0]), "r"(a[1]), "r"(a[2]), "r"(a[3]), "r"(b[0]), "r"(b[1]));
}

__device__ __forceinline__ float apply_act(float v, int ACT) {
    if (ACT == 1) return tanhf(v);
    if (ACT == 2) return 1.f / (1.f + expf(-v));
    if (ACT == 3) return DECAY_SCALE * (1.f / (1.f + expf(-v)));
    if (ACT == 4) return expf(DECAY_SCALE * (1.f / (1.f + expf(-v))));
    return v;
}

// ---------------- mix pre-pass: build the 6 token-shifted inputs ----------
__global__ void mix_kernel(const float* __restrict__ x,
                           const float* __restrict__ m_r, const float* __restrict__ m_w,
                           const float* __restrict__ m_k, const float* __restrict__ m_v,
                           const float* __restrict__ m_a, const float* __restrict__ m_g)
{
    int i = blockIdx.x * blockDim.x + threadIdx.x;   // float4 index
    if (i >= MM * DD / 4) return;
    int c4 = i & (DD / 4 - 1);
    int m  = i >> 8;
    int t  = m & (TT - 1);
    const float4* x4 = (const float4*)x;
    float4 xv = x4[i];
    float4 pv = t ? x4[i - DD / 4] : make_float4(0.f, 0.f, 0.f, 0.f);
    float4 d  = make_float4(pv.x - xv.x, pv.y - xv.y, pv.z - xv.z, pv.w - xv.w);

#define APPLY(MIX, OUT) { \
    float4 mm = ((const float4*)MIX)[c4]; \
    float4 o; \
    o.x = xv.x + d.x * mm.x; o.y = xv.y + d.y * mm.y; \
    o.z = xv.z + d.z * mm.z; o.w = xv.w + d.w * mm.w; \
    ((float4*)OUT)[i] = o; }
    APPLY(m_r, g_xr); APPLY(m_w, g_xw); APPLY(m_k, g_xk);
    APPLY(m_v, g_xv); APPLY(m_a, g_xa); APPLY(m_g, g_xg);
#undef APPLY
}

// ---------------- tf32 tensor-core GEMM, packed-fragment smem -------------
// A smem: [ks][rb][g][tg][quad], rb stride ARB=140 + bit-shuffled loader row
// map -> A STS 2-way banked. Fragment reads: LDS.128 / LDS.64 conflict-free.
template<int BN_, int WARPS_M, int WARPS_N, int ACT>
__global__ __launch_bounds__(256)
void gemm_tf32(const float* __restrict__ A, const float* __restrict__ B,
               float* __restrict__ C, int N, int K,
               const float* __restrict__ bias)
{
    constexpr int BM = 128, BK = 16;
    constexpr int WMT = BM / WARPS_M;
    constexpr int WNT = BN_ / WARPS_N;
    constexpr int MF = WMT / 16, NF = WNT / 8;
    constexpr int ARB = 140;
    constexpr int AKS = 8 * ARB;
    constexpr int ASZ = 2 * AKS;
    constexpr int BKS = BN_ * 8;
    constexpr int BSZ = 2 * BKS;
    constexpr int BQ    = BN_ / 4;
    constexpr int RLOAD = 256 / BQ;
    constexpr int PASS  = 16 / RLOAD;

    __shared__ alignas(16) float As[2][ASZ];
    __shared__ alignas(16) float Bs[2][BSZ];

    int tid  = threadIdx.x;
    int lane = tid & 31, warp = tid >> 5;
    int g  = lane >> 2, tg = lane & 3;
    int wm = (warp % WARPS_M) * WMT;
    int wn = (warp / WARPS_M) * WNT;
    int rb0 = wm >> 4;

    int rowBase = blockIdx.y * BM;
    int colBase = blockIdx.x * BN_;

    int t6 = tid & 63;
    int ll = t6 & 31, wbit = t6 >> 5;
    int arow = ((ll >> 2) & 3) * 16 + ((ll >> 1) & 1) * 8
             + ((ll & 1) + 2 * ((ll >> 4) & 1) + 4 * wbit);
    int ac4 = tid >> 6;
    int a_ks = ac4 >> 1, a_half = ac4 & 1;
    int bkr  = tid % RLOAD, bc4 = tid / RLOAD;

    float acc[MF][NF][4];
#pragma unroll
    for (int i = 0; i < MF; i++)
#pragma unroll
        for (int j = 0; j < NF; j++)
#pragma unroll
            for (int q = 0; q < 4; q++) acc[i][j][q] = 0.f;

    float4 ra[2], rbv[PASS];
    const int kTiles = K / BK;

#define LOAD_TILE(KT) { \
    _Pragma("unroll") \
    for (int p = 0; p < 2; p++) { \
        int r = rowBase + arow + p * 64; \
        ra[p] = *(const float4*)(A + (size_t)r * K + (KT) * BK + ac4 * 4); \
    } \
    _Pragma("unroll") \
    for (int p = 0; p < PASS; p++) { \
        int kr = bkr + p * RLOAD; \
        int cc = colBase + bc4 * 4; \
        rbv[p] = (cc < N) ? *(const float4*)(B + (size_t)((KT) * BK + kr) * N + cc) \
                          : make_float4(0.f, 0.f, 0.f, 0.f); \
    } }

#define STORE_TILE(BUF) { \
    _Pragma("unroll") \
    for (int p = 0; p < 2; p++) { \
        int r = arow + 64 * p; \
        int rb = r >> 4, gg = r & 7, hi = (r >> 3) & 1; \
        float* d = &As[BUF][a_ks * AKS + rb * ARB + gg * 16 + hi + 2 * a_half]; \
        d[0]  = f2tf32(ra[p].x); d[4]  = f2tf32(ra[p].y); \
        d[8]  = f2tf32(ra[p].z); d[12] = f2tf32(ra[p].w); \
    } \
    _Pragma("unroll") \
    for (int p = 0; p < PASS; p++) { \
        int kr = bkr + p * RLOAD; \
        int ks = kr >> 3, kl = kr & 7, btg = kl & 3, hs = kl >> 2; \
        float* d = &Bs[BUF][ks * BKS + (bc4 * 4) * 8 + btg * 2 + hs]; \
        d[0]  = f2tf32(rbv[p].x); d[8]  = f2tf32(rbv[p].y); \
        d[16] = f2tf32(rbv[p].z); d[24] = f2tf32(rbv[p].w); \
    } }

    LOAD_TILE(0);
    STORE_TILE(0);
    __syncthreads();

    int cur = 0;
    for (int kt = 1; kt <= kTiles; kt++) {
        if (kt < kTiles) LOAD_TILE(kt);

#pragma unroll
        for (int ks = 0; ks < 2; ks++) {
            unsigned af[MF][4], bf[NF][2];
#pragma unroll
            for (int i = 0; i < MF; i++) {
                float4 v = *(const float4*)&As[cur][ks * AKS + (rb0 + i) * ARB + g * 16 + tg * 4];
                af[i][0] = __float_as_uint(v.x); af[i][1] = __float_as_uint(v.y);
                af[i][2] = __float_as_uint(v.z); af[i][3] = __float_as_uint(v.w);
            }
#pragma unroll
            for (int j = 0; j < NF; j++) {
                float2 v = *(const float2*)&Bs[cur][ks * BKS + (wn + j * 8 + g) * 8 + tg * 2];
                bf[j][0] = __float_as_uint(v.x); bf[j][1] = __float_as_uint(v.y);
            }
#pragma unroll
            for (int i = 0; i < MF; i++)
#pragma unroll
                for (int j = 0; j < NF; j++)
                    mma_tf32(acc[i][j], af[i], bf[j]);
        }

        if (kt < kTiles) {
            int nxt = cur ^ 1;
            STORE_TILE(nxt);
        }
        __syncthreads();
        cur ^= 1;
    }
#undef LOAD_TILE
#undef STORE_TILE

#pragma unroll
    for (int i = 0; i < MF; i++) {
#pragma unroll
        for (int j = 0; j < NF; j++) {
            int r0 = rowBase + wm + i * 16 + g;
            int c0 = colBase + wn + j * 8 + 2 * tg;
#pragma unroll
            for (int q = 0; q < 4; q++) {
                int rr = r0 + (q >> 1) * 8;
                int cc = c0 + (q & 1);
                if (cc < N) {
                    float v = acc[i][j][q];
                    if (bias) v += bias[cc];
                    v = apply_act(v, ACT);
                    C[(size_t)rr * N + cc] = v;
                }
            }
        }
    }
}

// ---------------- prep: kk = l2norm(k*k_k); b = kk*a; nk = -kk; k rescale --
__global__ void prep_kernel(const float* __restrict__ k_k,
                            const float* __restrict__ k_a)
{
    int hidx = blockIdx.x;             // MM*HH
    int m = hidx >> 4, h = hidx & 15;
    int lane = threadIdx.x;            // 32
    size_t base = (size_t)m * DD + h * HDIM;
    int d0 = h * HDIM + lane, d1 = d0 + 32;

    float k0 = g_k[base + lane], k1 = g_k[base + lane + 32];
    float q0 = k0 * k_k[d0],     q1 = k1 * k_k[d1];
    float ss = q0 * q0 + q1 * q1;
#pragma unroll
    for (int o = 16; o > 0; o >>= 1) ss += __shfl_xor_sync(0xffffffffu, ss, o);
    float inv = 1.f / fmaxf(sqrtf(ss), 1e-12f);
    float kk0 = q0 * inv, kk1 = q1 * inv;

    float a0 = g_a[base + lane], a1 = g_a[base + lane + 32];
    g_kk[base + lane]      = -kk0;
    g_kk[base + lane + 32] = -kk1;
    g_b[base + lane]       = kk0 * a0;
    g_b[base + lane + 32]  = kk1 * a1;
    g_k[base + lane]       = k0 * (1.f + (a0 - 1.f) * k_a[d0]);
    g_k[base + lane + 32]  = k1 * (1.f + (a1 - 1.f) * k_a[d1]);
}

// ---------------- pair scalars: c1 = b_t·nk_{t+1}, c2 = k_t·nk_{t+1} -------
// one warp per (bh, even-t pair). 65536 warps, 8 warps/block.
__global__ __launch_bounds__(256)
void cpair_kernel()
{
    int wid  = blockIdx.x * 8 + (threadIdx.x >> 5);   // 0..65535
    int lane = threadIdx.x & 31;
    int tp = wid & (TPAIR - 1);
    int bh = wid >> 10;               // TPAIR = 1024
    int b = bh >> 4, h = bh & 15;
    size_t p1 = ((size_t)b * TT + 2 * tp) * DD + h * HDIM;
    size_t p2 = p1 + DD;

    float bb0 = g_b[p1 + lane],      bb1 = g_b[p1 + lane + 32];
    float kk0 = g_k[p1 + lane],      kk1 = g_k[p1 + lane + 32];
    float nn0 = g_kk[p2 + lane],     nn1 = g_kk[p2 + lane + 32];
    float c1 = bb0 * nn0 + bb1 * nn1;
    float c2 = kk0 * nn0 + kk1 * nn1;
#pragma unroll
    for (int o = 16; o > 0; o >>= 1) {
        c1 += __shfl_xor_sync(0xffffffffu, c1, o);
        c2 += __shfl_xor_sync(0xffffffffu, c2, o);
    }
    if (lane == 0) {
        g_c1[(size_t)bh * TPAIR + tp] = c1;
        g_c2[(size_t)bh * TPAIR + tp] = c2;
    }
}

// ---------------- sequential delta-rule scan v5: paired lookahead ----------
// Processes 2 steps per iteration. pa2 expanded via precomputed c1,c2 so both
// state-dots (d1 = S·nk1, d2 = S·(w1∘nk2)) shfl-reduce CONCURRENTLY, halving
// the serial reduction latency. Memory pattern = round-8 proven (coalesced
// float2 -> smem publish; 2-pair register prefetch, static slot indices).
#define GROUPS 16
#define ROWS   4
__global__ void scan_kernel()
{
    int idx = blockIdx.x;
    int g  = idx & (GROUPS - 1);
    int bh = idx >> 4;
    int b = bh >> 4, h = bh & 15;
    int tid = threadIdx.x;
    int row = tid >> 3;       // 0..3
    int c   = tid & 7;        // 0..7
    int c0  = c * 8;
    int j2  = tid * 2;

    __shared__ alignas(16) float SW1[2][64], SW2[2][64], SR1[2][64], SR2[2][64],
        SK1[2][64], SK2[2][64], SB1[2][64], SB2[2][64], SN1[2][64], SN2[2][64],
        SV[2][8];

    float S[8];
#pragma unroll
    for (int j = 0; j < 8; j++) S[j] = 0.f;

    size_t basebh = ((size_t)b * TT) * DD + h * HDIM;
    const float* pc1 = g_c1 + (size_t)bh * TPAIR;
    const float* pc2 = g_c2 + (size_t)bh * TPAIR;
    int vsel = (tid & 4) ? DD : 0;
    int vidx = g * ROWS + (tid & 3);

    float2 Aw1, Aw2, Ar1, Ar2, Ak1, Ak2, Ab1, Ab2, An1, An2; float Av, Ac1, Ac2;
    float2 Bw1, Bw2, Br1, Br2, Bk1, Bk2, Bb1, Bb2, Bn1, Bn2; float Bv, Bc1, Bc2;

#define LOADP(P, TP) { \
    size_t pb = basebh + (size_t)(2 * (TP)) * DD; \
    P##w1 = *(const float2*)(g_w  + pb + j2); P##w2 = *(const float2*)(g_w  + pb + DD + j2); \
    P##r1 = *(const float2*)(g_r  + pb + j2); P##r2 = *(const float2*)(g_r  + pb + DD + j2); \
    P##k1 = *(const float2*)(g_k  + pb + j2); P##k2 = *(const float2*)(g_k  + pb + DD + j2); \
    P##b1 = *(const float2*)(g_b  + pb + j2); P##b2 = *(const float2*)(g_b  + pb + DD + j2); \
    P##n1 = *(const float2*)(g_kk + pb + j2); P##n2 = *(const float2*)(g_kk + pb + DD + j2); \
    if (tid < 8) P##v = g_v[pb + vsel + vidx]; \
    P##c1 = pc1[TP]; P##c2 = pc2[TP]; }

#define PUBLISH(P, BUF) { \
    *(float2*)&SW1[BUF][j2] = P##w1; *(float2*)&SW2[BUF][j2] = P##w2; \
    *(float2*)&SR1[BUF][j2] = P##r1; *(float2*)&SR2[BUF][j2] = P##r2; \
    *(float2*)&SK1[BUF][j2] = P##k1; *(float2*)&SK2[BUF][j2] = P##k2; \
    *(float2*)&SB1[BUF][j2] = P##b1; *(float2*)&SB2[BUF][j2] = P##b2; \
    *(float2*)&SN1[BUF][j2] = P##n1; *(float2*)&SN2[BUF][j2] = P##n2; \
    if (tid < 8) SV[BUF][tid] = P##v; }

#define PAIR(P, BUF, TP) { \
    float cc1 = P##c1, cc2 = P##c2; \
    __syncwarp(); \
    if ((TP) + 2 < TPAIR) LOADP(P, (TP) + 2); \
    float v1 = SV[BUF][row], v2 = SV[BUF][4 + row]; \
    float d1a = 0.f, d1b = 0.f, d2a = 0.f, d2b = 0.f; \
    _Pragma("unroll") \
    for (int j = 0; j < 4; j++) { \
        d1a = fmaf(S[j], SN1[BUF][c0 + j], d1a); \
        d2a = fmaf(S[j], SW1[BUF][c0 + j] * SN2[BUF][c0 + j], d2a); \
    } \
    _Pragma("unroll") \
    for (int j = 4; j < 8; j++) { \
        d1b = fmaf(S[j], SN1[BUF][c0 + j], d1b); \
        d2b = fmaf(S[j], SW1[BUF][c0 + j] * SN2[BUF][c0 + j], d2b); \
    } \
    float d1 = d1a + d1b, d2 = d2a + d2b; \
    d1 += __shfl_xor_sync(0xffffffffu, d1, 1); d2 += __shfl_xor_sync(0xffffffffu, d2, 1); \
    d1 += __shfl_xor_sync(0xffffffffu, d1, 2); d2 += __shfl_xor_sync(0xffffffffu, d2, 2); \
    d1 += __shfl_xor_sync(0xffffffffu, d1, 4); d2 += __shfl_xor_sync(0xffffffffu, d2, 4); \
    float pa1 = d1; \
    float pa2 = fmaf(pa1, cc1, fmaf(v1, cc2, d2)); \
    float po1a = 0.f, po1b = 0.f, po2a = 0.f, po2b = 0.f; \
    _Pragma("unroll") \
    for (int j = 0; j < 8; j++) { \
        int kc = c0 + j; \
        float s1 = fmaf(S[j], SW1[BUF][kc], fmaf(pa1, SB1[BUF][kc], v1 * SK1[BUF][kc])); \
        float s2 = fmaf(s1,   SW2[BUF][kc], fmaf(pa2, SB2[BUF][kc], v2 * SK2[BUF][kc])); \
        S[j] = s2; \
        if (j < 4) { po1a = fmaf(s1, SR1[BUF][kc], po1a); po2a = fmaf(s2, SR2[BUF][kc], po2a); } \
        else       { po1b = fmaf(s1, SR1[BUF][kc], po1b); po2b = fmaf(s2, SR2[BUF][kc], po2b); } \
    } \
    float po1 = po1a + po1b, po2 = po2a + po2b; \
    po1 += __shfl_xor_sync(0xffffffffu, po1, 1); po2 += __shfl_xor_sync(0xffffffffu, po2, 1); \
    po1 += __shfl_xor_sync(0xffffffffu, po1, 2); po2 += __shfl_xor_sync(0xffffffffu, po2, 2); \
    po1 += __shfl_xor_sync(0xffffffffu, po1, 4); po2 += __shfl_xor_sync(0xffffffffu, po2, 4); \
    if (c == 0) { \
        size_t ob = basebh + (size_t)(2 * (TP)) * DD + g * ROWS + row; \
        g_o[ob] = po1; g_o[ob + DD] = po2; \
    } }

    LOADP(A, 0);
    LOADP(B, 1);
    PUBLISH(A, 0);
    for (int tp = 0; tp < TPAIR; tp += 2) {
        PUBLISH(B, 1);            // buf1 safe: last read one pair ago, shfl-converged
        PAIR(A, 0, tp);           // syncwarp inside; refills A with pair tp+2
        if (tp + 2 < TPAIR) PUBLISH(A, 0);   // buf0 reads done (shfl convergence)
        PAIR(B, 1, tp + 1);       // refills B with pair tp+3
    }
#undef LOADP
#undef PUBLISH
#undef PAIR
}

// ---------------- post: GroupNorm(head) + corr + gate ---------------------
__global__ void post_kernel(const float* __restrict__ r_k,
                            const float* __restrict__ gnw,
                            const float* __restrict__ gnb)
{
    int hidx = blockIdx.x;
    int m = hidx >> 4, h = hidx & 15;
    int lane = threadIdx.x;
    size_t base = (size_t)m * DD + h * HDIM;
    int d0 = h * HDIM + lane, d1 = d0 + 32;

    float o0 = g_o[base + lane], o1 = g_o[base + lane + 32];
    float s = o0 + o1;
#pragma unroll
    for (int o = 16; o > 0; o >>= 1) s += __shfl_xor_sync(0xffffffffu, s, o);
    float mu = s * (1.f / 64.f);
    float e0 = o0 - mu, e1 = o1 - mu;
    float vs = e0 * e0 + e1 * e1;
#pragma unroll
    for (int o = 16; o > 0; o >>= 1) vs += __shfl_xor_sync(0xffffffffu, vs, o);
    float inv = rsqrtf(vs * (1.f / 64.f) + GN_EPS);

    float on0 = e0 * inv * gnw[d0] + gnb[d0];
    float on1 = e1 * inv * gnw[d1] + gnb[d1];

    float dot = g_r[base + lane]      * g_k[base + lane]      * r_k[d0]
              + g_r[base + lane + 32] * g_k[base + lane + 32] * r_k[d1];
#pragma unroll
    for (int o = 16; o > 0; o >>= 1) dot += __shfl_xor_sync(0xffffffffu, dot, o);

    g_y[base + lane]      = (on0 + dot * g_v[base + lane])      * g_g[base + lane];
    g_y[base + lane + 32] = (on1 + dot * g_v[base + lane + 32]) * g_g[base + lane + 32];
}

// ---------------------------------------------------------------------------
extern "C" void kernel_launch(void* const* d_in, const int* in_sizes, int n_in,
                              void* d_out, int out_size)
{
    const float* x     = (const float*)d_in[0];
    const float* mix_r = (const float*)d_in[1];
    const float* mix_w = (const float*)d_in[2];
    const float* mix_k = (const float*)d_in[3];
    const float* mix_v = (const float*)d_in[4];
    const float* mix_a = (const float*)d_in[5];
    const float* mix_g = (const float*)d_in[6];
    const float* k_k   = (const float*)d_in[7];
    const float* k_a   = (const float*)d_in[8];
    const float* r_k   = (const float*)d_in[9];
    const float* Wr    = (const float*)d_in[10];
    const float* Wk    = (const float*)d_in[11];
    const float* Wv    = (const float*)d_in[12];
    const float* Wo    = (const float*)d_in[13];
    const float* wA    = (const float*)d_in[14];
    const float* wB    = (const float*)d_in[15];
    const float* w_bias= (const float*)d_in[16];
    const float* aA    = (const float*)d_in[17];
    const float* aB    = (const float*)d_in[18];
    const float* a_bias= (const float*)d_in[19];
    const float* gA    = (const float*)d_in[20];
    const float* gB    = (const float*)d_in[21];
    const float* gnw   = (const float*)d_in[22];
    const float* gnb   = (const float*)d_in[23];
    float* out = (float*)d_out;

    float *pxr, *pxw, *pxk, *pxv, *pxa, *pxg;
    float *pr, *pw, *pk, *pv, *pa, *pg, *py, *puw, *pua, *pug;
    cudaGetSymbolAddress((void**)&pxr, g_xr);
    cudaGetSymbolAddress((void**)&pxw, g_xw);
    cudaGetSymbolAddress((void**)&pxk, g_xk);
    cudaGetSymbolAddress((void**)&pxv, g_xv);
    cudaGetSymbolAddress((void**)&pxa, g_xa);
    cudaGetSymbolAddress((void**)&pxg, g_xg);
    cudaGetSymbolAddress((void**)&pr,  g_r);
    cudaGetSymbolAddress((void**)&pw,  g_w);
    cudaGetSymbolAddress((void**)&pk,  g_k);
    cudaGetSymbolAddress((void**)&pv,  g_v);
    cudaGetSymbolAddress((void**)&pa,  g_a);
    cudaGetSymbolAddress((void**)&pg,  g_g);
    cudaGetSymbolAddress((void**)&py,  g_y);
    cudaGetSymbolAddress((void**)&puw, g_uw);
    cudaGetSymbolAddress((void**)&pua, g_ua);
    cudaGetSymbolAddress((void**)&pug, g_ug);

    // 1. token-shift mix -> 6 mixed inputs
    mix_kernel<<<MM * DD / 4 / 256, 256>>>(x, mix_r, mix_w, mix_k, mix_v, mix_a, mix_g);

    dim3 blk(256);
    dim3 grdBig(DD / 128, MM / 128);            // (8, 64) : N=1024
    dim3 grdUp64(1, MM / 128);                  // (1, 64) : N=64
    dim3 grdUp160((LOW_G + 63) / 64, MM / 128); // (3, 64) : N=160

    // 2. big projections (tf32 tensor cores)
    gemm_tf32<128,2,4,0><<<grdBig, blk>>>(pxr, Wr, pr, DD, DD, nullptr);
    gemm_tf32<128,2,4,0><<<grdBig, blk>>>(pxk, Wk, pk, DD, DD, nullptr);
    gemm_tf32<128,2,4,0><<<grdBig, blk>>>(pxv, Wv, pv, DD, DD, nullptr);

    // 3. w lora: tanh(xw@wA) @ wB + bias -> exp(DECAY_SCALE*sigmoid(.)) fused
    gemm_tf32<64,4,2,1><<<grdUp64, blk>>>(pxw, wA, puw, LOW_W, DD, nullptr);
    gemm_tf32<128,2,4,4><<<grdBig, blk>>>(puw, wB, pw, DD, LOW_W, w_bias);

    // 4. a lora: (xa@aA) @ aB + bias -> sigmoid
    gemm_tf32<64,4,2,0><<<grdUp64, blk>>>(pxa, aA, pua, LOW_A, DD, nullptr);
    gemm_tf32<128,2,4,2><<<grdBig, blk>>>(pua, aB, pa, DD, LOW_A, a_bias);

    // 5. g lora: sigmoid(xg@gA) @ gB
    gemm_tf32<64,4,2,2><<<grdUp160, blk>>>(pxg, gA, pug, LOW_G, DD, nullptr);
    gemm_tf32<128,2,4,0><<<grdBig, blk>>>(pug, gB, pg, DD, LOW_G, nullptr);

    // 6. kk normalize + b/nk precompute + k rescale
    prep_kernel<<<MM * HH, 32>>>(k_k, k_a);

    // 7. pair scalars for the lookahead scan
    cpair_kernel<<<BB * HH * TPAIR / 8, 256>>>();

    // 8. sequential generalized delta-rule scan (v5: paired lookahead)
    scan_kernel<<<BB * HH * GROUPS, 32>>>();

    // 9. GroupNorm + correction + gate
    post_kernel<<<MM * HH, 32>>>(r_k, gnw, gnb);

    // 10. output projection
    gemm_tf32<128,2,4,0><<<grdBig, blk>>>(py, Wo, out, DD, DD, nullptr);
}

// round 14
// speedup vs baseline: 1.1352x; 1.0390x over previous
#include <cuda_runtime.h>
#include <math.h>

#define BB 4
#define TT 2048
#define DD 1024
#define HH 16
#define HDIM 64
#define MM (BB*TT)   /* 8192 */
#define LOW_W 64
#define LOW_A 64
#define LOW_G 160
#define DECAY_SCALE (-0.6065306597126334f)
#define GN_EPS (64.0f*1e-5f)
#define TPAIR (TT/2)

// ---------------- scratch (device globals: allocation is banned) ----------
__device__ float g_xr[MM*DD];
__device__ float g_xw[MM*DD];
__device__ float g_xk[MM*DD];
__device__ float g_xv[MM*DD];
__device__ float g_xa[MM*DD];
__device__ float g_xg[MM*DD];
__device__ float g_r [MM*DD];
__device__ float g_w [MM*DD];   // holds exp(w) after the w GEMM (ACT=4)
__device__ float g_k [MM*DD];
__device__ float g_v [MM*DD];
__device__ float g_a [MM*DD];
__device__ float g_g [MM*DD];
__device__ float g_kk[MM*DD];   // holds -kk (normalized) after prep
__device__ float g_b [MM*DD];   // holds kk*a after prep
__device__ float g_o [MM*DD];
__device__ float g_y [MM*DD];
__device__ float g_uw[MM*LOW_W];
__device__ float g_ua[MM*LOW_A];
__device__ float g_ug[MM*LOW_G];
__device__ float g_c1[BB*HH*TPAIR];   // b_t · nk_{t+1} per even t
__device__ float g_c2[BB*HH*TPAIR];   // k_t · nk_{t+1} per even t

// ---------------- helpers -------------------------------------------------
__device__ __forceinline__ float f2tf32(float x) {
    unsigned u;
    asm("cvt.rna.tf32.f32 %0, %1;" : "=r"(u) : "f"(x));
    return __uint_as_float(u);
}

__device__ __forceinline__ void mma_tf32(float* c, const unsigned* a, const unsigned* b) {
    asm volatile(
        "mma.sync.aligned.m16n8k8.row.col.f32.tf32.tf32.f32 "
        "{%0,%1,%2,%3}, {%4,%5,%6,%7}, {%8,%9}, {%0,%1,%2,%3};\n"
        : "+f"(c[0]), "+f"(c[1]), "+f"(c[2]), "+f"(c[3])
        : "r"(a[0]), "r"(a[1]), "r"(a[2]), "r"(a[3]), "r"(b[0]), "r"(b[1]));
}

__device__ __forceinline__ float apply_act(float v, int ACT) {
    if (ACT == 1) return tanhf(v);
    if (ACT == 2) return 1.f / (1.f + expf(-v));
    if (ACT == 3) return DECAY_SCALE * (1.f / (1.f + expf(-v)));
    if (ACT == 4) return expf(DECAY_SCALE * (1.f / (1.f + expf(-v))));
    return v;
}

// ---------------- mix pre-pass: build the 6 token-shifted inputs ----------
__global__ void mix_kernel(const float* __restrict__ x,
                           const float* __restrict__ m_r, const float* __restrict__ m_w,
                           const float* __restrict__ m_k, const float* __restrict__ m_v,
                           const float* __restrict__ m_a, const float* __restrict__ m_g)
{
    int i = blockIdx.x * blockDim.x + threadIdx.x;   // float4 index
    if (i >= MM * DD / 4) return;
    int c4 = i & (DD / 4 - 1);
    int m  = i >> 8;
    int t  = m & (TT - 1);
    const float4* x4 = (const float4*)x;
    float4 xv = x4[i];
    float4 pv = t ? x4[i - DD / 4] : make_float4(0.f, 0.f, 0.f, 0.f);
    float4 d  = make_float4(pv.x - xv.x, pv.y - xv.y, pv.z - xv.z, pv.w - xv.w);

#define APPLY(MIX, OUT) { \
    float4 mm = ((const float4*)MIX)[c4]; \
    float4 o; \
    o.x = xv.x + d.x * mm.x; o.y = xv.y + d.y * mm.y; \
    o.z = xv.z + d.z * mm.z; o.w = xv.w + d.w * mm.w; \
    ((float4*)OUT)[i] = o; }
    APPLY(m_r, g_xr); APPLY(m_w, g_xw); APPLY(m_k, g_xk);
    APPLY(m_v, g_xv); APPLY(m_a, g_xa); APPLY(m_g, g_xg);
#undef APPLY
}

// ---------------- tf32 tensor-core GEMM, packed-fragment smem -------------
// A smem: [ks][rb][g][tg][quad], rb stride ARB=140 + bit-shuffled loader row
// map -> A STS 2-way banked. Fragment reads: LDS.128 / LDS.64 conflict-free.
template<int BN_, int WARPS_M, int WARPS_N, int ACT>
__global__ __launch_bounds__(256)
void gemm_tf32(const float* __restrict__ A, const float* __restrict__ B,
               float* __restrict__ C, int N, int K,
               const float* __restrict__ bias)
{
    constexpr int BM = 128, BK = 16;
    constexpr int WMT = BM / WARPS_M;
    constexpr int WNT = BN_ / WARPS_N;
    constexpr int MF = WMT / 16, NF = WNT / 8;
    constexpr int ARB = 140;
    constexpr int AKS = 8 * ARB;
    constexpr int ASZ = 2 * AKS;
    constexpr int BKS = BN_ * 8;
    constexpr int BSZ = 2 * BKS;
    constexpr int BQ    = BN_ / 4;
    constexpr int RLOAD = 256 / BQ;
    constexpr int PASS  = 16 / RLOAD;

    __shared__ alignas(16) float As[2][ASZ];
    __shared__ alignas(16) float Bs[2][BSZ];

    int tid  = threadIdx.x;
    int lane = tid & 31, warp = tid >> 5;
    int g  = lane >> 2, tg = lane & 3;
    int wm = (warp % WARPS_M) * WMT;
    int wn = (warp / WARPS_M) * WNT;
    int rb0 = wm >> 4;

    int rowBase = blockIdx.y * BM;
    int colBase = blockIdx.x * BN_;

    int t6 = tid & 63;
    int ll = t6 & 31, wbit = t6 >> 5;
    int arow = ((ll >> 2) & 3) * 16 + ((ll >> 1) & 1) * 8
             + ((ll & 1) + 2 * ((ll >> 4) & 1) + 4 * wbit);
    int ac4 = tid >> 6;
    int a_ks = ac4 >> 1, a_half = ac4 & 1;
    int bkr  = tid % RLOAD, bc4 = tid / RLOAD;

    float acc[MF][NF][4];
#pragma unroll
    for (int i = 0; i < MF; i++)
#pragma unroll
        for (int j = 0; j < NF; j++)
#pragma unroll
            for (int q = 0; q < 4; q++) acc[i][j][q] = 0.f;

    float4 ra[2], rbv[PASS];
    const int kTiles = K / BK;

#define LOAD_TILE(KT) { \
    _Pragma("unroll") \
    for (int p = 0; p < 2; p++) { \
        int r = rowBase + arow + p * 64; \
        ra[p] = *(const float4*)(A + (size_t)r * K + (KT) * BK + ac4 * 4); \
    } \
    _Pragma("unroll") \
    for (int p = 0; p < PASS; p++) { \
        int kr = bkr + p * RLOAD; \
        int cc = colBase + bc4 * 4; \
        rbv[p] = (cc < N) ? *(const float4*)(B + (size_t)((KT) * BK + kr) * N + cc) \
                          : make_float4(0.f, 0.f, 0.f, 0.f); \
    } }

#define STORE_TILE(BUF) { \
    _Pragma("unroll") \
    for (int p = 0; p < 2; p++) { \
        int r = arow + 64 * p; \
        int rb = r >> 4, gg = r & 7, hi = (r >> 3) & 1; \
        float* d = &As[BUF][a_ks * AKS + rb * ARB + gg * 16 + hi + 2 * a_half]; \
        d[0]  = f2tf32(ra[p].x); d[4]  = f2tf32(ra[p].y); \
        d[8]  = f2tf32(ra[p].z); d[12] = f2tf32(ra[p].w); \
    } \
    _Pragma("unroll") \
    for (int p = 0; p < PASS; p++) { \
        int kr = bkr + p * RLOAD; \
        int ks = kr >> 3, kl = kr & 7, btg = kl & 3, hs = kl >> 2; \
        float* d = &Bs[BUF][ks * BKS + (bc4 * 4) * 8 + btg * 2 + hs]; \
        d[0]  = f2tf32(rbv[p].x); d[8]  = f2tf32(rbv[p].y); \
        d[16] = f2tf32(rbv[p].z); d[24] = f2tf32(rbv[p].w); \
    } }

    LOAD_TILE(0);
    STORE_TILE(0);
    __syncthreads();

    int cur = 0;
    for (int kt = 1; kt <= kTiles; kt++) {
        if (kt < kTiles) LOAD_TILE(kt);

#pragma unroll
        for (int ks = 0; ks < 2; ks++) {
            unsigned af[MF][4], bf[NF][2];
#pragma unroll
            for (int i = 0; i < MF; i++) {
                float4 v = *(const float4*)&As[cur][ks * AKS + (rb0 + i) * ARB + g * 16 + tg * 4];
                af[i][0] = __float_as_uint(v.x); af[i][1] = __float_as_uint(v.y);
                af[i][2] = __float_as_uint(v.z); af[i][3] = __float_as_uint(v.w);
            }
#pragma unroll
            for (int j = 0; j < NF; j++) {
                float2 v = *(const float2*)&Bs[cur][ks * BKS + (wn + j * 8 + g) * 8 + tg * 2];
                bf[j][0] = __float_as_uint(v.x); bf[j][1] = __float_as_uint(v.y);
            }
#pragma unroll
            for (int i = 0; i < MF; i++)
#pragma unroll
                for (int j = 0; j < NF; j++)
                    mma_tf32(acc[i][j], af[i], bf[j]);
        }

        if (kt < kTiles) {
            int nxt = cur ^ 1;
            STORE_TILE(nxt);
        }
        __syncthreads();
        cur ^= 1;
    }
#undef LOAD_TILE
#undef STORE_TILE

#pragma unroll
    for (int i = 0; i < MF; i++) {
#pragma unroll
        for (int j = 0; j < NF; j++) {
            int r0 = rowBase + wm + i * 16 + g;
            int c0 = colBase + wn + j * 8 + 2 * tg;
#pragma unroll
            for (int q = 0; q < 4; q++) {
                int rr = r0 + (q >> 1) * 8;
                int cc = c0 + (q & 1);
                if (cc < N) {
                    float v = acc[i][j][q];
                    if (bias) v += bias[cc];
                    v = apply_act(v, ACT);
                    C[(size_t)rr * N + cc] = v;
                }
            }
        }
    }
}

// ---------------- FUSED LoRA up-GEMMs: one launch for w/a/g ---------------
// grid.x: 0 -> wA (N=64, tanh), 1 -> aA (N=64, none), 2..4 -> gA (N=160,
// sigmoid, colBase=(x-2)*64). BN=64, WARPS(4,2) proven config; runtime act.
struct UpF {
    const float* A[3];
    const float* B[3];
    float*       C[3];
    int          N[3];
    int          act[3];
};
__global__ __launch_bounds__(256)
void gemm_up_fused(UpF p, int K)
{
    constexpr int BM = 128, BK = 16, BN_ = 64;
    constexpr int WARPS_M = 4, WARPS_N = 2;
    constexpr int WMT = BM / WARPS_M, WNT = BN_ / WARPS_N;
    constexpr int MF = WMT / 16, NF = WNT / 8;
    constexpr int ARB = 140;
    constexpr int AKS = 8 * ARB;
    constexpr int ASZ = 2 * AKS;
    constexpr int BKS = BN_ * 8;
    constexpr int BSZ = 2 * BKS;
    constexpr int BQ = BN_ / 4, RLOAD = 256 / BQ, PASS = 16 / RLOAD;

    __shared__ alignas(16) float As[2][ASZ];
    __shared__ alignas(16) float Bs[2][BSZ];

    int bx = blockIdx.x;
    int seg = (bx == 0) ? 0 : (bx == 1) ? 1 : 2;
    int colBase = (bx >= 2) ? (bx - 2) * BN_ : 0;
    const float* A = p.A[seg];
    const float* B = p.B[seg];
    float*       C = p.C[seg];
    int N   = p.N[seg];
    int act = p.act[seg];

    int tid  = threadIdx.x;
    int lane = tid & 31, warp = tid >> 5;
    int g  = lane >> 2, tg = lane & 3;
    int wm = (warp % WARPS_M) * WMT;
    int wn = (warp / WARPS_M) * WNT;
    int rb0 = wm >> 4;

    int rowBase = blockIdx.y * BM;

    int t6 = tid & 63;
    int ll = t6 & 31, wbit = t6 >> 5;
    int arow = ((ll >> 2) & 3) * 16 + ((ll >> 1) & 1) * 8
             + ((ll & 1) + 2 * ((ll >> 4) & 1) + 4 * wbit);
    int ac4 = tid >> 6;
    int a_ks = ac4 >> 1, a_half = ac4 & 1;
    int bkr  = tid % RLOAD, bc4 = tid / RLOAD;

    float acc[MF][NF][4];
#pragma unroll
    for (int i = 0; i < MF; i++)
#pragma unroll
        for (int j = 0; j < NF; j++)
#pragma unroll
            for (int q = 0; q < 4; q++) acc[i][j][q] = 0.f;

    float4 ra[2], rbv[PASS];
    const int kTiles = K / BK;

#define LOAD_TILE(KT) { \
    _Pragma("unroll") \
    for (int p4 = 0; p4 < 2; p4++) { \
        int r = rowBase + arow + p4 * 64; \
        ra[p4] = *(const float4*)(A + (size_t)r * K + (KT) * BK + ac4 * 4); \
    } \
    _Pragma("unroll") \
    for (int p4 = 0; p4 < PASS; p4++) { \
        int kr = bkr + p4 * RLOAD; \
        int cc = colBase + bc4 * 4; \
        rbv[p4] = (cc < N) ? *(const float4*)(B + (size_t)((KT) * BK + kr) * N + cc) \
                           : make_float4(0.f, 0.f, 0.f, 0.f); \
    } }

#define STORE_TILE(BUF) { \
    _Pragma("unroll") \
    for (int p4 = 0; p4 < 2; p4++) { \
        int r = arow + 64 * p4; \
        int rb = r >> 4, gg = r & 7, hi = (r >> 3) & 1; \
        float* d = &As[BUF][a_ks * AKS + rb * ARB + gg * 16 + hi + 2 * a_half]; \
        d[0]  = f2tf32(ra[p4].x); d[4]  = f2tf32(ra[p4].y); \
        d[8]  = f2tf32(ra[p4].z); d[12] = f2tf32(ra[p4].w); \
    } \
    _Pragma("unroll") \
    for (int p4 = 0; p4 < PASS; p4++) { \
        int kr = bkr + p4 * RLOAD; \
        int ks = kr >> 3, kl = kr & 7, btg = kl & 3, hs = kl >> 2; \
        float* d = &Bs[BUF][ks * BKS + (bc4 * 4) * 8 + btg * 2 + hs]; \
        d[0]  = f2tf32(rbv[p4].x); d[8]  = f2tf32(rbv[p4].y); \
        d[16] = f2tf32(rbv[p4].z); d[24] = f2tf32(rbv[p4].w); \
    } }

    LOAD_TILE(0);
    STORE_TILE(0);
    __syncthreads();

    int cur = 0;
    for (int kt = 1; kt <= kTiles; kt++) {
        if (kt < kTiles) LOAD_TILE(kt);

#pragma unroll
        for (int ks = 0; ks < 2; ks++) {
            unsigned af[MF][4], bf[NF][2];
#pragma unroll
            for (int i = 0; i < MF; i++) {
                float4 v = *(const float4*)&As[cur][ks * AKS + (rb0 + i) * ARB + g * 16 + tg * 4];
                af[i][0] = __float_as_uint(v.x); af[i][1] = __float_as_uint(v.y);
                af[i][2] = __float_as_uint(v.z); af[i][3] = __float_as_uint(v.w);
            }
#pragma unroll
            for (int j = 0; j < NF; j++) {
                float2 v = *(const float2*)&Bs[cur][ks * BKS + (wn + j * 8 + g) * 8 + tg * 2];
                bf[j][0] = __float_as_uint(v.x); bf[j][1] = __float_as_uint(v.y);
            }
#pragma unroll
            for (int i = 0; i < MF; i++)
#pragma unroll
                for (int j = 0; j < NF; j++)
                    mma_tf32(acc[i][j], af[i], bf[j]);
        }

        if (kt < kTiles) {
            int nxt = cur ^ 1;
            STORE_TILE(nxt);
        }
        __syncthreads();
        cur ^= 1;
    }
#undef LOAD_TILE
#undef STORE_TILE

#pragma unroll
    for (int i = 0; i < MF; i++) {
#pragma unroll
        for (int j = 0; j < NF; j++) {
            int r0 = rowBase + wm + i * 16 + g;
            int c0 = colBase + wn + j * 8 + 2 * tg;
#pragma unroll
            for (int q = 0; q < 4; q++) {
                int rr = r0 + (q >> 1) * 8;
                int cc = c0 + (q & 1);
                if (cc < N) {
                    float v = apply_act(acc[i][j][q], act);
                    C[(size_t)rr * N + cc] = v;
                }
            }
        }
    }
}

// ---------------- prep: kk = l2norm(k*k_k); b = kk*a; nk = -kk; k rescale --
__global__ void prep_kernel(const float* __restrict__ k_k,
                            const float* __restrict__ k_a)
{
    int hidx = blockIdx.x;             // MM*HH
    int m = hidx >> 4, h = hidx & 15;
    int lane = threadIdx.x;            // 32
    size_t base = (size_t)m * DD + h * HDIM;
    int d0 = h * HDIM + lane, d1 = d0 + 32;

    float k0 = g_k[base + lane], k1 = g_k[base + lane + 32];
    float q0 = k0 * k_k[d0],     q1 = k1 * k_k[d1];
    float ss = q0 * q0 + q1 * q1;
#pragma unroll
    for (int o = 16; o > 0; o >>= 1) ss += __shfl_xor_sync(0xffffffffu, ss, o);
    float inv = 1.f / fmaxf(sqrtf(ss), 1e-12f);
    float kk0 = q0 * inv, kk1 = q1 * inv;

    float a0 = g_a[base + lane], a1 = g_a[base + lane + 32];
    g_kk[base + lane]      = -kk0;
    g_kk[base + lane + 32] = -kk1;
    g_b[base + lane]       = kk0 * a0;
    g_b[base + lane + 32]  = kk1 * a1;
    g_k[base + lane]       = k0 * (1.f + (a0 - 1.f) * k_a[d0]);
    g_k[base + lane + 32]  = k1 * (1.f + (a1 - 1.f) * k_a[d1]);
}

// ---------------- pair scalars: c1 = b_t·nk_{t+1}, c2 = k_t·nk_{t+1} -------
__global__ __launch_bounds__(256)
void cpair_kernel()
{
    int wid  = blockIdx.x * 8 + (threadIdx.x >> 5);   // 0..65535
    int lane = threadIdx.x & 31;
    int tp = wid & (TPAIR - 1);
    int bh = wid >> 10;               // TPAIR = 1024
    int b = bh >> 4, h = bh & 15;
    size_t p1 = ((size_t)b * TT + 2 * tp) * DD + h * HDIM;
    size_t p2 = p1 + DD;

    float bb0 = g_b[p1 + lane],      bb1 = g_b[p1 + lane + 32];
    float kk0 = g_k[p1 + lane],      kk1 = g_k[p1 + lane + 32];
    float nn0 = g_kk[p2 + lane],     nn1 = g_kk[p2 + lane + 32];
    float c1 = bb0 * nn0 + bb1 * nn1;
    float c2 = kk0 * nn0 + kk1 * nn1;
#pragma unroll
    for (int o = 16; o > 0; o >>= 1) {
        c1 += __shfl_xor_sync(0xffffffffu, c1, o);
        c2 += __shfl_xor_sync(0xffffffffu, c2, o);
    }
    if (lane == 0) {
        g_c1[(size_t)bh * TPAIR + tp] = c1;
        g_c2[(size_t)bh * TPAIR + tp] = c2;
    }
}

// ---------------- sequential delta-rule scan v5: paired lookahead ----------
#define GROUPS 16
#define ROWS   4
__global__ void scan_kernel()
{
    int idx = blockIdx.x;
    int g  = idx & (GROUPS - 1);
    int bh = idx >> 4;
    int b = bh >> 4, h = bh & 15;
    int tid = threadIdx.x;
    int row = tid >> 3;       // 0..3
    int c   = tid & 7;        // 0..7
    int c0  = c * 8;
    int j2  = tid * 2;

    __shared__ alignas(16) float SW1[2][64], SW2[2][64], SR1[2][64], SR2[2][64],
        SK1[2][64], SK2[2][64], SB1[2][64], SB2[2][64], SN1[2][64], SN2[2][64],
        SV[2][8];

    float S[8];
#pragma unroll
    for (int j = 0; j < 8; j++) S[j] = 0.f;

    size_t basebh = ((size_t)b * TT) * DD + h * HDIM;
    const float* pc1 = g_c1 + (size_t)bh * TPAIR;
    const float* pc2 = g_c2 + (size_t)bh * TPAIR;
    int vsel = (tid & 4) ? DD : 0;
    int vidx = g * ROWS + (tid & 3);

    float2 Aw1, Aw2, Ar1, Ar2, Ak1, Ak2, Ab1, Ab2, An1, An2; float Av, Ac1, Ac2;
    float2 Bw1, Bw2, Br1, Br2, Bk1, Bk2, Bb1, Bb2, Bn1, Bn2; float Bv, Bc1, Bc2;

#define LOADP(P, TP) { \
    size_t pb = basebh + (size_t)(2 * (TP)) * DD; \
    P##w1 = *(const float2*)(g_w  + pb + j2); P##w2 = *(const float2*)(g_w  + pb + DD + j2); \
    P##r1 = *(const float2*)(g_r  + pb + j2); P##r2 = *(const float2*)(g_r  + pb + DD + j2); \
    P##k1 = *(const float2*)(g_k  + pb + j2); P##k2 = *(const float2*)(g_k  + pb + DD + j2); \
    P##b1 = *(const float2*)(g_b  + pb + j2); P##b2 = *(const float2*)(g_b  + pb + DD + j2); \
    P##n1 = *(const float2*)(g_kk + pb + j2); P##n2 = *(const float2*)(g_kk + pb + DD + j2); \
    if (tid < 8) P##v = g_v[pb + vsel + vidx]; \
    P##c1 = pc1[TP]; P##c2 = pc2[TP]; }

#define PUBLISH(P, BUF) { \
    *(float2*)&SW1[BUF][j2] = P##w1; *(float2*)&SW2[BUF][j2] = P##w2; \
    *(float2*)&SR1[BUF][j2] = P##r1; *(float2*)&SR2[BUF][j2] = P##r2; \
    *(float2*)&SK1[BUF][j2] = P##k1; *(float2*)&SK2[BUF][j2] = P##k2; \
    *(float2*)&SB1[BUF][j2] = P##b1; *(float2*)&SB2[BUF][j2] = P##b2; \
    *(float2*)&SN1[BUF][j2] = P##n1; *(float2*)&SN2[BUF][j2] = P##n2; \
    if (tid < 8) SV[BUF][tid] = P##v; }

#define PAIR(P, BUF, TP) { \
    float cc1 = P##c1, cc2 = P##c2; \
    __syncwarp(); \
    if ((TP) + 2 < TPAIR) LOADP(P, (TP) + 2); \
    float v1 = SV[BUF][row], v2 = SV[BUF][4 + row]; \
    float d1a = 0.f, d1b = 0.f, d2a = 0.f, d2b = 0.f; \
    _Pragma("unroll") \
    for (int j = 0; j < 4; j++) { \
        d1a = fmaf(S[j], SN1[BUF][c0 + j], d1a); \
        d2a = fmaf(S[j], SW1[BUF][c0 + j] * SN2[BUF][c0 + j], d2a); \
    } \
    _Pragma("unroll") \
    for (int j = 4; j < 8; j++) { \
        d1b = fmaf(S[j], SN1[BUF][c0 + j], d1b); \
        d2b = fmaf(S[j], SW1[BUF][c0 + j] * SN2[BUF][c0 + j], d2b); \
    } \
    float d1 = d1a + d1b, d2 = d2a + d2b; \
    d1 += __shfl_xor_sync(0xffffffffu, d1, 1); d2 += __shfl_xor_sync(0xffffffffu, d2, 1); \
    d1 += __shfl_xor_sync(0xffffffffu, d1, 2); d2 += __shfl_xor_sync(0xffffffffu, d2, 2); \
    d1 += __shfl_xor_sync(0xffffffffu, d1, 4); d2 += __shfl_xor_sync(0xffffffffu, d2, 4); \
    float pa1 = d1; \
    float pa2 = fmaf(pa1, cc1, fmaf(v1, cc2, d2)); \
    float po1a = 0.f, po1b = 0.f, po2a = 0.f, po2b = 0.f; \
    _Pragma("unroll") \
    for (int j = 0; j < 8; j++) { \
        int kc = c0 + j; \
        float s1 = fmaf(S[j], SW1[BUF][kc], fmaf(pa1, SB1[BUF][kc], v1 * SK1[BUF][kc])); \
        float s2 = fmaf(s1,   SW2[BUF][kc], fmaf(pa2, SB2[BUF][kc], v2 * SK2[BUF][kc])); \
        S[j] = s2; \
        if (j < 4) { po1a = fmaf(s1, SR1[BUF][kc], po1a); po2a = fmaf(s2, SR2[BUF][kc], po2a); } \
        else       { po1b = fmaf(s1, SR1[BUF][kc], po1b); po2b = fmaf(s2, SR2[BUF][kc], po2b); } \
    } \
    float po1 = po1a + po1b, po2 = po2a + po2b; \
    po1 += __shfl_xor_sync(0xffffffffu, po1, 1); po2 += __shfl_xor_sync(0xffffffffu, po2, 1); \
    po1 += __shfl_xor_sync(0xffffffffu, po1, 2); po2 += __shfl_xor_sync(0xffffffffu, po2, 2); \
    po1 += __shfl_xor_sync(0xffffffffu, po1, 4); po2 += __shfl_xor_sync(0xffffffffu, po2, 4); \
    if (c == 0) { \
        size_t ob = basebh + (size_t)(2 * (TP)) * DD + g * ROWS + row; \
        g_o[ob] = po1; g_o[ob + DD] = po2; \
    } }

    LOADP(A, 0);
    LOADP(B, 1);
    PUBLISH(A, 0);
    for (int tp = 0; tp < TPAIR; tp += 2) {
        PUBLISH(B, 1);
        PAIR(A, 0, tp);
        if (tp + 2 < TPAIR) PUBLISH(A, 0);
        PAIR(B, 1, tp + 1);
    }
#undef LOADP
#undef PUBLISH
#undef PAIR
}

// ---------------- post: GroupNorm(head) + corr + gate ---------------------
__global__ void post_kernel(const float* __restrict__ r_k,
                            const float* __restrict__ gnw,
                            const float* __restrict__ gnb)
{
    int hidx = blockIdx.x;
    int m = hidx >> 4, h = hidx & 15;
    int lane = threadIdx.x;
    size_t base = (size_t)m * DD + h * HDIM;
    int d0 = h * HDIM + lane, d1 = d0 + 32;

    float o0 = g_o[base + lane], o1 = g_o[base + lane + 32];
    float s = o0 + o1;
#pragma unroll
    for (int o = 16; o > 0; o >>= 1) s += __shfl_xor_sync(0xffffffffu, s, o);
    float mu = s * (1.f / 64.f);
    float e0 = o0 - mu, e1 = o1 - mu;
    float vs = e0 * e0 + e1 * e1;
#pragma unroll
    for (int o = 16; o > 0; o >>= 1) vs += __shfl_xor_sync(0xffffffffu, vs, o);
    float inv = rsqrtf(vs * (1.f / 64.f) + GN_EPS);

    float on0 = e0 * inv * gnw[d0] + gnb[d0];
    float on1 = e1 * inv * gnw[d1] + gnb[d1];

    float dot = g_r[base + lane]      * g_k[base + lane]      * r_k[d0]
              + g_r[base + lane + 32] * g_k[base + lane + 32] * r_k[d1];
#pragma unroll
    for (int o = 16; o > 0; o >>= 1) dot += __shfl_xor_sync(0xffffffffu, dot, o);

    g_y[base + lane]      = (on0 + dot * g_v[base + lane])      * g_g[base + lane];
    g_y[base + lane + 32] = (on1 + dot * g_v[base + lane + 32]) * g_g[base + lane + 32];
}

// ---------------------------------------------------------------------------
extern "C" void kernel_launch(void* const* d_in, const int* in_sizes, int n_in,
                              void* d_out, int out_size)
{
    const float* x     = (const float*)d_in[0];
    const float* mix_r = (const float*)d_in[1];
    const float* mix_w = (const float*)d_in[2];
    const float* mix_k = (const float*)d_in[3];
    const float* mix_v = (const float*)d_in[4];
    const float* mix_a = (const float*)d_in[5];
    const float* mix_g = (const float*)d_in[6];
    const float* k_k   = (const float*)d_in[7];
    const float* k_a   = (const float*)d_in[8];
    const float* r_k   = (const float*)d_in[9];
    const float* Wr    = (const float*)d_in[10];
    const float* Wk    = (const float*)d_in[11];
    const float* Wv    = (const float*)d_in[12];
    const float* Wo    = (const float*)d_in[13];
    const float* wA    = (const float*)d_in[14];
    const float* wB    = (const float*)d_in[15];
    const float* w_bias= (const float*)d_in[16];
    const float* aA    = (const float*)d_in[17];
    const float* aB    = (const float*)d_in[18];
    const float* a_bias= (const float*)d_in[19];
    const float* gA    = (const float*)d_in[20];
    const float* gB    = (const float*)d_in[21];
    const float* gnw   = (const float*)d_in[22];
    const float* gnb   = (const float*)d_in[23];
    float* out = (float*)d_out;

    float *pxr, *pxw, *pxk, *pxv, *pxa, *pxg;
    float *pr, *pw, *pk, *pv, *pa, *pg, *py, *puw, *pua, *pug;
    cudaGetSymbolAddress((void**)&pxr, g_xr);
    cudaGetSymbolAddress((void**)&pxw, g_xw);
    cudaGetSymbolAddress((void**)&pxk, g_xk);
    cudaGetSymbolAddress((void**)&pxv, g_xv);
    cudaGetSymbolAddress((void**)&pxa, g_xa);
    cudaGetSymbolAddress((void**)&pxg, g_xg);
    cudaGetSymbolAddress((void**)&pr,  g_r);
    cudaGetSymbolAddress((void**)&pw,  g_w);
    cudaGetSymbolAddress((void**)&pk,  g_k);
    cudaGetSymbolAddress((void**)&pv,  g_v);
    cudaGetSymbolAddress((void**)&pa,  g_a);
    cudaGetSymbolAddress((void**)&pg,  g_g);
    cudaGetSymbolAddress((void**)&py,  g_y);
    cudaGetSymbolAddress((void**)&puw, g_uw);
    cudaGetSymbolAddress((void**)&pua, g_ua);
    cudaGetSymbolAddress((void**)&pug, g_ug);

    // 1. token-shift mix -> 6 mixed inputs
    mix_kernel<<<MM * DD / 4 / 256, 256>>>(x, mix_r, mix_w, mix_k, mix_v, mix_a, mix_g);

    dim3 blk(256);
    dim3 grdBig(DD / 128, MM / 128);            // (8, 64) : N=1024
    dim3 grdUpF(5, MM / 128);                   // fused w/a/g ups: 320 blocks

    // 2. big projections (tf32 tensor cores)
    gemm_tf32<128,2,4,0><<<grdBig, blk>>>(pxr, Wr, pr, DD, DD, nullptr);
    gemm_tf32<128,2,4,0><<<grdBig, blk>>>(pxk, Wk, pk, DD, DD, nullptr);
    gemm_tf32<128,2,4,0><<<grdBig, blk>>>(pxv, Wv, pv, DD, DD, nullptr);

    // 3. all three LoRA up-projections in ONE launch (occupancy fix)
    {
        UpF p;
        p.A[0] = pxw; p.B[0] = wA; p.C[0] = puw; p.N[0] = LOW_W; p.act[0] = 1;
        p.A[1] = pxa; p.B[1] = aA; p.C[1] = pua; p.N[1] = LOW_A; p.act[1] = 0;
        p.A[2] = pxg; p.B[2] = gA; p.C[2] = pug; p.N[2] = LOW_G; p.act[2] = 2;
        gemm_up_fused<<<grdUpF, blk>>>(p, DD);
    }

    // 4. LoRA down-projections
    gemm_tf32<128,2,4,4><<<grdBig, blk>>>(puw, wB, pw, DD, LOW_W, w_bias);
    gemm_tf32<128,2,4,2><<<grdBig, blk>>>(pua, aB, pa, DD, LOW_A, a_bias);
    gemm_tf32<128,2,4,0><<<grdBig, blk>>>(pug, gB, pg, DD, LOW_G, nullptr);

    // 5. kk normalize + b/nk precompute + k rescale
    prep_kernel<<<MM * HH, 32>>>(k_k, k_a);

    // 6. pair scalars for the lookahead scan
    cpair_kernel<<<BB * HH * TPAIR / 8, 256>>>();

    // 7. sequential generalized delta-rule scan (v5: paired lookahead)
    scan_kernel<<<BB * HH * GROUPS, 32>>>();

    // 8. GroupNorm + correction + gate
    post_kernel<<<MM * HH, 32>>>(r_k, gnw, gnb);

    // 9. output projection
    gemm_tf32<128,2,4,0><<<grdBig, blk>>>(py, Wo, out, DD, DD, nullptr);
}